// round 5
// baseline (speedup 1.0000x reference)
#include <cuda_runtime.h>

#define THREADS 256
#define DIMV 32
#define NHV 24
#define KLV 31   // dim-1 stacked layers

// shared weight-buffer offsets (floats)
#define OW1 0      // W1 transposed [j][h] : 32*24 = 768
#define OW2 768    // W2 [H][h]           : 576
#define OW3 1344   // W3 [H][h]           : 576
#define OW4 1920   // W4 [o][h]           : 48
#define OB1 1968   // 24
#define OB2 1992   // 24
#define OB3 2016   // 24
#define OB4 2040   // 2
#define WTOT 2042

__device__ __forceinline__ float lrelu(float v) { return fmaxf(v, 0.2f * v); }

__global__ void __launch_bounds__(THREADS, 2)
maf_kernel(const float* __restrict__ x,  const float* __restrict__ p0,
           const float* __restrict__ W1, const float* __restrict__ b1,
           const float* __restrict__ W2, const float* __restrict__ b2,
           const float* __restrict__ W3, const float* __restrict__ b3,
           const float* __restrict__ W4, const float* __restrict__ b4,
           float* __restrict__ z, float* __restrict__ logdet)
{
    __shared__ float xs[THREADS * 33];   // x rows, stride 33 => conflict-free scalar LDS
    __shared__ float wbuf[2048];         // per-k weights (single buffer, reg-prefetched)

    const int tid = threadIdx.x;
    const size_t b = (size_t)blockIdx.x * THREADS + tid;

    // ---- load this thread's x row into padded shared ----
    {
        const float4* xr = reinterpret_cast<const float4*>(x + b * DIMV);
        #pragma unroll
        for (int q = 0; q < 8; q++) {
            float4 v = xr[q];
            xs[tid * 33 + 4 * q + 0] = v.x;
            xs[tid * 33 + 4 * q + 1] = v.y;
            xs[tid * 33 + 4 * q + 2] = v.z;
            xs[tid * 33 + 4 * q + 3] = v.w;
        }
    }

    // cooperative weight fetch for stacked layer k: 2042 floats, 8 per thread
    auto wload = [&](int k, float* r) {
        #pragma unroll
        for (int i = 0; i < 8; i++) {
            int f = tid + i * THREADS;
            float v = 0.f;
            if (f < 768)        v = W1[k * 768 + f];
            else if (f < 1344)  v = W2[k * 576 + (f - 768)];
            else if (f < 1920)  v = W3[k * 576 + (f - 1344)];
            else if (f < 1968)  v = W4[k * 48  + (f - 1920)];
            else if (f < 1992)  v = b1[k * 24  + (f - 1968)];
            else if (f < 2016)  v = b2[k * 24  + (f - 1992)];
            else if (f < 2040)  v = b3[k * 24  + (f - 2016)];
            else if (f < WTOT)  v = b4[k * 2   + (f - 2040)];
            r[i] = v;
        }
    };
    // store to shared; W1 is transposed to [j][h] so layer-1 inner loop is
    // contiguous-in-h (LDS128-able, broadcast across the warp)
    auto wstore = [&](const float* r) {
        #pragma unroll
        for (int i = 0; i < 8; i++) {
            int f = tid + i * THREADS;
            int dst = f;
            if (f < 768) { int h = f >> 5, j = f & 31; dst = j * NHV + h; }
            if (f < WTOT) wbuf[dst] = r[i];
        }
    };

    { float r[8]; wload(0, r); wstore(r); }
    __syncthreads();

    float ldet = 0.f;
    float a[NHV], h2[NHV];

    for (int k = 0; k < KLV; k++) {
        // prefetch next k's weights into registers (overlaps with compute below)
        float r[8];
        if (k + 1 < KLV) wload(k + 1, r);

        // ---- layer 1: h1[h] = lrelu( sum_{j<=k} W1[k][h][j] * x[j] + b1 ) ----
        #pragma unroll
        for (int h = 0; h < NHV; h++) a[h] = wbuf[OB1 + h];
        for (int j = 0; j <= k; j++) {
            float xv = xs[tid * 33 + j];
            const float4* w4 = reinterpret_cast<const float4*>(&wbuf[OW1 + j * NHV]);
            #pragma unroll
            for (int q = 0; q < 6; q++) {
                float4 w = w4[q];
                a[4 * q + 0] = fmaf(w.x, xv, a[4 * q + 0]);
                a[4 * q + 1] = fmaf(w.y, xv, a[4 * q + 1]);
                a[4 * q + 2] = fmaf(w.z, xv, a[4 * q + 2]);
                a[4 * q + 3] = fmaf(w.w, xv, a[4 * q + 3]);
            }
        }
        #pragma unroll
        for (int h = 0; h < NHV; h++) a[h] = lrelu(a[h]);

        // ---- layer 2 ----
        #pragma unroll
        for (int H = 0; H < NHV; H++) {
            const float4* w4 = reinterpret_cast<const float4*>(&wbuf[OW2 + H * NHV]);
            float acc0 = wbuf[OB2 + H], acc1 = 0.f;
            #pragma unroll
            for (int q = 0; q < 6; q++) {
                float4 w = w4[q];
                acc0 = fmaf(w.x, a[4 * q + 0], acc0);
                acc1 = fmaf(w.y, a[4 * q + 1], acc1);
                acc0 = fmaf(w.z, a[4 * q + 2], acc0);
                acc1 = fmaf(w.w, a[4 * q + 3], acc1);
            }
            h2[H] = lrelu(acc0 + acc1);
        }

        // ---- layer 3 ----
        #pragma unroll
        for (int H = 0; H < NHV; H++) {
            const float4* w4 = reinterpret_cast<const float4*>(&wbuf[OW3 + H * NHV]);
            float acc0 = wbuf[OB3 + H], acc1 = 0.f;
            #pragma unroll
            for (int q = 0; q < 6; q++) {
                float4 w = w4[q];
                acc0 = fmaf(w.x, h2[4 * q + 0], acc0);
                acc1 = fmaf(w.y, h2[4 * q + 1], acc1);
                acc0 = fmaf(w.z, h2[4 * q + 2], acc0);
                acc1 = fmaf(w.w, h2[4 * q + 3], acc1);
            }
            a[H] = lrelu(acc0 + acc1);
        }

        // ---- layer 4: (s, t) ----
        float sa = wbuf[OB4 + 0], sb = 0.f;
        float ta = wbuf[OB4 + 1], tb = 0.f;
        {
            const float4* ws = reinterpret_cast<const float4*>(&wbuf[OW4]);
            const float4* wt = reinterpret_cast<const float4*>(&wbuf[OW4 + NHV]);
            #pragma unroll
            for (int q = 0; q < 6; q++) {
                float4 w = ws[q];
                sa = fmaf(w.x, a[4 * q + 0], sa);
                sb = fmaf(w.y, a[4 * q + 1], sb);
                sa = fmaf(w.z, a[4 * q + 2], sa);
                sb = fmaf(w.w, a[4 * q + 3], sb);
                float4 v = wt[q];
                ta = fmaf(v.x, a[4 * q + 0], ta);
                tb = fmaf(v.y, a[4 * q + 1], tb);
                ta = fmaf(v.z, a[4 * q + 2], ta);
                tb = fmaf(v.w, a[4 * q + 3], tb);
            }
        }
        float sv = sa + sb, tv = ta + tb;
        ldet += sv;
        // i = k+1 ; order reversed => z column 31-(k+1) = 30-k
        float val = fmaf(xs[tid * 33 + (k + 1)], expf(sv), tv);
        z[b * DIMV + (30 - k)] = val;

        __syncthreads();                 // all readers done with current wbuf
        if (k + 1 < KLV) wstore(r);
        __syncthreads();                 // next wbuf visible
    }

    // dim 0: LeafParam p0
    float s0 = p0[0], t0 = p0[1];
    z[b * DIMV + 31] = fmaf(xs[tid * 33 + 0], expf(s0), t0);
    ldet += s0;
    if (logdet) logdet[b] = ldet;
}

extern "C" void kernel_launch(void* const* d_in, const int* in_sizes, int n_in,
                              void* d_out, int out_size)
{
    (void)n_in;
    const float* x  = (const float*)d_in[0];
    const float* p0 = (const float*)d_in[1];
    const float* W1 = (const float*)d_in[2];
    const float* b1 = (const float*)d_in[3];
    const float* W2 = (const float*)d_in[4];
    const float* b2 = (const float*)d_in[5];
    const float* W3 = (const float*)d_in[6];
    const float* b3 = (const float*)d_in[7];
    const float* W4 = (const float*)d_in[8];
    const float* b4 = (const float*)d_in[9];

    const int B = in_sizes[0] / DIMV;
    float* z  = (float*)d_out;
    float* ld = (out_size >= B * (DIMV + 1)) ? z + (size_t)B * DIMV : nullptr;

    maf_kernel<<<B / THREADS, THREADS>>>(x, p0, W1, b1, W2, b2, W3, b3, W4, b4, z, ld);
}

// round 7
// speedup vs baseline: 2.3873x; 2.3873x over previous
#include <cuda_runtime.h>
#include <cstdint>

#define THREADS 128
#define DIMV 32
#define NHV 24
#define NP 12      // packed h-pairs per 24
#define KLV 31     // dim-1 stacked layers

// shared weight-buffer offsets (floats) — W1 transposed to [j][h]
#define OW1 0      // 32*24 = 768
#define OW2 768    // 576
#define OW3 1344   // 576
#define OW4 1920   // 48
#define OB1 1968   // 24
#define OB2 1992   // 24
#define OB3 2016   // 24
#define OB4 2040   // 2
#define WTOT 2042

// ---- packed f32x2 helpers (sm_100+) ----
__device__ __forceinline__ void ffma2(uint64_t& c, uint64_t a, uint64_t b) {
    asm("fma.rn.f32x2 %0, %1, %2, %0;" : "+l"(c) : "l"(a), "l"(b));
}
__device__ __forceinline__ uint64_t pack2(float lo, float hi) {
    uint64_t r; asm("mov.b64 %0, {%1, %2};" : "=l"(r) : "f"(lo), "f"(hi)); return r;
}
__device__ __forceinline__ void unpack2(uint64_t v, float& lo, float& hi) {
    asm("mov.b64 {%0, %1}, %2;" : "=f"(lo), "=f"(hi) : "l"(v));
}
__device__ __forceinline__ uint64_t lrelu2(uint64_t v) {
    float lo, hi; unpack2(v, lo, hi);
    lo = fmaxf(lo, 0.2f * lo);
    hi = fmaxf(hi, 0.2f * hi);
    return pack2(lo, hi);
}
__device__ __forceinline__ float lrelu(float v) { return fmaxf(v, 0.2f * v); }

__global__ void __launch_bounds__(THREADS, 2)
maf_kernel(const float* __restrict__ x,  const float* __restrict__ p0,
           const float* __restrict__ W1, const float* __restrict__ b1,
           const float* __restrict__ W2, const float* __restrict__ b2,
           const float* __restrict__ W3, const float* __restrict__ b3,
           const float* __restrict__ W4, const float* __restrict__ b4,
           float* __restrict__ z, float* __restrict__ logdet)
{
    // 256 rows per block (2 per thread), stride-33 padded => conflict-free
    __shared__ float xs[THREADS * 2 * 33];
    __shared__ float wbuf[2048];     // per-k weights (single buffer, reg-prefetched)

    const int tid = threadIdx.x;
    const size_t r0 = ((size_t)blockIdx.x * THREADS + tid) * 2;   // global row 0
    const int lr0 = 2 * tid, lr1 = 2 * tid + 1;                   // local xs rows

    // ---- load both x rows into padded shared (thread-private, no sync needed) ----
    {
        const float4* xa = reinterpret_cast<const float4*>(x + r0 * DIMV);
        const float4* xb = reinterpret_cast<const float4*>(x + (r0 + 1) * DIMV);
        #pragma unroll
        for (int q = 0; q < 8; q++) {
            float4 v = xa[q];
            xs[lr0 * 33 + 4 * q + 0] = v.x;  xs[lr0 * 33 + 4 * q + 1] = v.y;
            xs[lr0 * 33 + 4 * q + 2] = v.z;  xs[lr0 * 33 + 4 * q + 3] = v.w;
            float4 w = xb[q];
            xs[lr1 * 33 + 4 * q + 0] = w.x;  xs[lr1 * 33 + 4 * q + 1] = w.y;
            xs[lr1 * 33 + 4 * q + 2] = w.z;  xs[lr1 * 33 + 4 * q + 3] = w.w;
        }
    }

    // cooperative weight fetch for stacked layer k: 2042 floats, 16 per thread
    auto wload = [&](int k, float* r) {
        #pragma unroll
        for (int i = 0; i < 16; i++) {
            int f = tid + i * THREADS;
            float v = 0.f;
            if (f < 768)        v = W1[k * 768 + f];
            else if (f < 1344)  v = W2[k * 576 + (f - 768)];
            else if (f < 1920)  v = W3[k * 576 + (f - 1344)];
            else if (f < 1968)  v = W4[k * 48  + (f - 1920)];
            else if (f < 1992)  v = b1[k * 24  + (f - 1968)];
            else if (f < 2016)  v = b2[k * 24  + (f - 1992)];
            else if (f < 2040)  v = b3[k * 24  + (f - 2016)];
            else if (f < WTOT)  v = b4[k * 2   + (f - 2040)];
            r[i] = v;
        }
    };
    // W1 is transposed to [j][h] so layer-1 weights are contiguous-in-h (h-pair packable)
    auto wstore = [&](const float* r) {
        #pragma unroll
        for (int i = 0; i < 16; i++) {
            int f = tid + i * THREADS;
            int dst = f;
            if (f < 768) { int h = f >> 5, j = f & 31; dst = j * NHV + h; }
            if (f < WTOT) wbuf[dst] = r[i];
        }
    };

    { float r[16]; wload(0, r); wstore(r); }
    __syncthreads();

    float ldet0 = 0.f, ldet1 = 0.f;
    uint64_t A0[NP], A1[NP];   // packed h-pair activations, rows 0/1
    uint64_t B0[NP], B1[NP];

    for (int k = 0; k < KLV; k++) {
        // prefetch next k's weights into registers (overlaps with compute below)
        float pr[16];
        if (k + 1 < KLV) wload(k + 1, pr);

        // ---- layer 1: A[h] = lrelu( sum_{j<=k} W1T[j][h] * x[j] + b1[h] ) ----
        #pragma unroll
        for (int p = 0; p < NP; p++) {
            uint64_t bb = *reinterpret_cast<const uint64_t*>(&wbuf[OB1 + 2 * p]);
            A0[p] = bb; A1[p] = bb;
        }
        for (int j = 0; j <= k; j++) {
            float x0 = xs[lr0 * 33 + j], x1 = xs[lr1 * 33 + j];
            uint64_t xx0 = pack2(x0, x0), xx1 = pack2(x1, x1);
            const ulonglong2* w = reinterpret_cast<const ulonglong2*>(&wbuf[OW1 + j * NHV]);
            #pragma unroll
            for (int q = 0; q < 6; q++) {
                ulonglong2 wp = w[q];               // LDS.128 = 2 packed weight pairs
                ffma2(A0[2 * q + 0], wp.x, xx0);
                ffma2(A0[2 * q + 1], wp.y, xx0);
                ffma2(A1[2 * q + 0], wp.x, xx1);
                ffma2(A1[2 * q + 1], wp.y, xx1);
            }
        }
        #pragma unroll
        for (int p = 0; p < NP; p++) { A0[p] = lrelu2(A0[p]); A1[p] = lrelu2(A1[p]); }

        // ---- layers 2 & 3: dense 24x24, h-pair packed, weights reused across rows ----
        #pragma unroll
        for (int Hp = 0; Hp < NP; Hp++) {
            float o0e, o0o, o1e, o1o;
            #pragma unroll
            for (int e = 0; e < 2; e++) {
                int H = 2 * Hp + e;
                const ulonglong2* w = reinterpret_cast<const ulonglong2*>(&wbuf[OW2 + H * NHV]);
                uint64_t s0 = 0, t0 = 0, s1 = 0, t1 = 0;
                #pragma unroll
                for (int q = 0; q < 6; q++) {
                    ulonglong2 wp = w[q];
                    ffma2(s0, wp.x, A0[2 * q + 0]);
                    ffma2(t0, wp.y, A0[2 * q + 1]);
                    ffma2(s1, wp.x, A1[2 * q + 0]);
                    ffma2(t1, wp.y, A1[2 * q + 1]);
                }
                float bH = wbuf[OB2 + H];
                float a, b2v, c, d;
                unpack2(s0, a, b2v); unpack2(t0, c, d);
                float v0 = lrelu((a + b2v) + (c + d) + bH);
                unpack2(s1, a, b2v); unpack2(t1, c, d);
                float v1 = lrelu((a + b2v) + (c + d) + bH);
                if (e == 0) { o0e = v0; o1e = v1; } else { o0o = v0; o1o = v1; }
            }
            B0[Hp] = pack2(o0e, o0o);
            B1[Hp] = pack2(o1e, o1o);
        }

        #pragma unroll
        for (int Hp = 0; Hp < NP; Hp++) {
            float o0e, o0o, o1e, o1o;
            #pragma unroll
            for (int e = 0; e < 2; e++) {
                int H = 2 * Hp + e;
                const ulonglong2* w = reinterpret_cast<const ulonglong2*>(&wbuf[OW3 + H * NHV]);
                uint64_t s0 = 0, t0 = 0, s1 = 0, t1 = 0;
                #pragma unroll
                for (int q = 0; q < 6; q++) {
                    ulonglong2 wp = w[q];
                    ffma2(s0, wp.x, B0[2 * q + 0]);
                    ffma2(t0, wp.y, B0[2 * q + 1]);
                    ffma2(s1, wp.x, B1[2 * q + 0]);
                    ffma2(t1, wp.y, B1[2 * q + 1]);
                }
                float bH = wbuf[OB3 + H];
                float a, b2v, c, d;
                unpack2(s0, a, b2v); unpack2(t0, c, d);
                float v0 = lrelu((a + b2v) + (c + d) + bH);
                unpack2(s1, a, b2v); unpack2(t1, c, d);
                float v1 = lrelu((a + b2v) + (c + d) + bH);
                if (e == 0) { o0e = v0; o1e = v1; } else { o0o = v0; o1o = v1; }
            }
            A0[Hp] = pack2(o0e, o0o);
            A1[Hp] = pack2(o1e, o1o);
        }

        // ---- layer 4: (s, t) per row ----
        float sv0, tv0, sv1, tv1;
        #pragma unroll
        for (int o = 0; o < 2; o++) {
            const ulonglong2* w = reinterpret_cast<const ulonglong2*>(&wbuf[OW4 + o * NHV]);
            uint64_t s0 = 0, t0 = 0, s1 = 0, t1 = 0;
            #pragma unroll
            for (int q = 0; q < 6; q++) {
                ulonglong2 wp = w[q];
                ffma2(s0, wp.x, A0[2 * q + 0]);
                ffma2(t0, wp.y, A0[2 * q + 1]);
                ffma2(s1, wp.x, A1[2 * q + 0]);
                ffma2(t1, wp.y, A1[2 * q + 1]);
            }
            float bo = wbuf[OB4 + o];
            float a, b2v, c, d;
            unpack2(s0, a, b2v); unpack2(t0, c, d);
            float v0 = (a + b2v) + (c + d) + bo;
            unpack2(s1, a, b2v); unpack2(t1, c, d);
            float v1 = (a + b2v) + (c + d) + bo;
            if (o == 0) { sv0 = v0; sv1 = v1; } else { tv0 = v0; tv1 = v1; }
        }

        ldet0 += sv0; ldet1 += sv1;
        // i = k+1 ; reversed order => z column 31-(k+1) = 30-k
        z[r0 * DIMV + (30 - k)]       = fmaf(xs[lr0 * 33 + (k + 1)], __expf(sv0), tv0);
        z[(r0 + 1) * DIMV + (30 - k)] = fmaf(xs[lr1 * 33 + (k + 1)], __expf(sv1), tv1);

        __syncthreads();                  // all readers done with current wbuf
        if (k + 1 < KLV) wstore(pr);
        __syncthreads();                  // next wbuf visible
    }

    // dim 0: LeafParam p0 (reversed order => column 31)
    float s0v = p0[0], t0v = p0[1];
    float e0 = __expf(s0v);
    z[r0 * DIMV + 31]       = fmaf(xs[lr0 * 33 + 0], e0, t0v);
    z[(r0 + 1) * DIMV + 31] = fmaf(xs[lr1 * 33 + 0], e0, t0v);
    ldet0 += s0v; ldet1 += s0v;
    if (logdet) { logdet[r0] = ldet0; logdet[r0 + 1] = ldet1; }
}

extern "C" void kernel_launch(void* const* d_in, const int* in_sizes, int n_in,
                              void* d_out, int out_size)
{
    (void)n_in;
    const float* x  = (const float*)d_in[0];
    const float* p0 = (const float*)d_in[1];
    const float* W1 = (const float*)d_in[2];
    const float* b1 = (const float*)d_in[3];
    const float* W2 = (const float*)d_in[4];
    const float* b2 = (const float*)d_in[5];
    const float* W3 = (const float*)d_in[6];
    const float* b3 = (const float*)d_in[7];
    const float* W4 = (const float*)d_in[8];
    const float* b4 = (const float*)d_in[9];

    const int B = in_sizes[0] / DIMV;
    float* z  = (float*)d_out;
    float* ld = (out_size >= B * (DIMV + 1)) ? z + (size_t)B * DIMV : nullptr;

    // 2 rows per thread, 128 threads => 256 rows per block
    maf_kernel<<<B / (THREADS * 2), THREADS>>>(x, p0, W1, b1, W2, b2, W3, b3, W4, b4, z, ld);
}